// round 16
// baseline (speedup 1.0000x reference)
#include <cuda_runtime.h>
#include <cuda_fp16.h>
#include <math.h>
#include <stdint.h>

#define BATCH 2
#define SEQ   2048
#define DIM   2048
#define NH    16
#define HD    128
#define QKV_N (3*DIM)
#define ROWS  (BATCH*SEQ)

// 1/sqrt(128) * log2(e) — folded into stored Q
#define QK_SCALE 0.12752798314985582f

// ---------------- scratch (device globals) ----------------
__device__ __half g_xh[(long long)ROWS * DIM];
__device__ __half g_wqkvh[(long long)DIM * QKV_N];
__device__ __half g_wprojh[(long long)DIM * DIM];
__device__ __half g_qnh[(long long)BATCH*NH*SEQ*HD];
__device__ __half g_knh[(long long)BATCH*NH*SEQ*HD];
__device__ __half g_vh [(long long)BATCH*NH*SEQ*HD];
__device__ __half g_oh [(long long)ROWS * DIM];

// ---------------- PTX helpers ----------------
__device__ __forceinline__ uint32_t smem_u32(const void* p) {
    return (uint32_t)__cvta_generic_to_shared(p);
}
__device__ __forceinline__ void ldsm_x4(uint32_t& r0, uint32_t& r1, uint32_t& r2, uint32_t& r3, uint32_t a) {
    asm volatile("ldmatrix.sync.aligned.m8n8.x4.shared.b16 {%0,%1,%2,%3}, [%4];"
                 : "=r"(r0), "=r"(r1), "=r"(r2), "=r"(r3) : "r"(a));
}
__device__ __forceinline__ void ldsm_x4_t(uint32_t& r0, uint32_t& r1, uint32_t& r2, uint32_t& r3, uint32_t a) {
    asm volatile("ldmatrix.sync.aligned.m8n8.x4.trans.shared.b16 {%0,%1,%2,%3}, [%4];"
                 : "=r"(r0), "=r"(r1), "=r"(r2), "=r"(r3) : "r"(a));
}
__device__ __forceinline__ void mma_f16(float* d, const uint32_t* a, uint32_t b0, uint32_t b1) {
    asm volatile("mma.sync.aligned.m16n8k16.row.col.f32.f16.f16.f32 "
                 "{%0,%1,%2,%3}, {%4,%5,%6,%7}, {%8,%9}, {%0,%1,%2,%3};"
                 : "+f"(d[0]), "+f"(d[1]), "+f"(d[2]), "+f"(d[3])
                 : "r"(a[0]), "r"(a[1]), "r"(a[2]), "r"(a[3]), "r"(b0), "r"(b1));
}
__device__ __forceinline__ void cp16(uint32_t dst, const void* src) {
    asm volatile("cp.async.cg.shared.global [%0], [%1], 16;" :: "r"(dst), "l"(src));
}
__device__ __forceinline__ void cp_commit() { asm volatile("cp.async.commit_group;"); }
__device__ __forceinline__ uint32_t pack_h2(float x, float y) {
    __half2 h = __floats2half2_rn(x, y);
    return *(uint32_t*)&h;
}

// ---------------- merged fp32 -> fp16 converter ----------------
#define CN0 ((long long)ROWS * DIM / 8)
#define CN1 ((long long)DIM * QKV_N / 8)
#define CN2 ((long long)DIM * DIM / 8)

__global__ __launch_bounds__(256) void convert_all(
    const float* __restrict__ x,  const float* __restrict__ w1, const float* __restrict__ w2,
    __half* __restrict__ xo, __half* __restrict__ w1o, __half* __restrict__ w2o)
{
    long long i = (long long)blockIdx.x * 256 + threadIdx.x;
    const float* s; __half* d; long long j;
    if (i < CN0)            { s = x;  d = xo;  j = i; }
    else if (i < CN0 + CN1) { s = w1; d = w1o; j = i - CN0; }
    else                    { s = w2; d = w2o; j = i - CN0 - CN1; }
    const float4* s4 = (const float4*)s;
    float4 v0 = s4[2*j], v1 = s4[2*j + 1];
    uint4 o;
    o.x = pack_h2(v0.x, v0.y); o.y = pack_h2(v0.z, v0.w);
    o.z = pack_h2(v1.x, v1.y); o.w = pack_h2(v1.z, v1.w);
    ((uint4*)d)[j] = o;
}

// ---------------------------------------------------------------------------
// fp16 GEMM (NN): C_f32 = A_h[M,K] @ B_h[K,N] + bias
// 128x128 CTA tile, 256 threads (8 warps, warp tile 32x64), GBK=64,
// 3-stage cp.async with R12's 2-sync skeleton (load BEFORE wait, depth 2).
// MODE 0: fp32 out + bias
// MODE 1: fused QKV epilogue (tile = one head); Q rms pre-scaled by QK_SCALE.
// ---------------------------------------------------------------------------
#define GBK 64
#define LDA_H 72
#define LDB_H 136
#define STG_A (128 * LDA_H)          // 9216 halves
#define STG_B (GBK * LDB_H)          // 8704 halves
#define STG_SZ (STG_A + STG_B)       // 17920 halves
#define NSTG 3
#define GEMM_SMEM (NSTG * STG_SZ * 2)    // 107520 B

template<int MODE>
__global__ __launch_bounds__(256, 2) void gemm_f16(
    const __half* __restrict__ A, const __half* __restrict__ B,
    const float* __restrict__ bias, float* __restrict__ C,
    int K, int lda, int ldb, int ldc,
    const float* __restrict__ pe,
    const float* __restrict__ q_scale, const float* __restrict__ k_scale,
    __half* __restrict__ Qn, __half* __restrict__ Kn, __half* __restrict__ Vh)
{
    extern __shared__ __half dynsm[];

    const int tid = threadIdx.x, lane = tid & 31, warp = tid >> 5;
    const int wm = warp & 3, wn = warp >> 2;
    const long long row0 = (long long)blockIdx.y * 128;
    const int col0 = blockIdx.x * 128;

    float acc[2][8][4];
    #pragma unroll
    for (int i = 0; i < 2; i++)
        #pragma unroll
        for (int j = 0; j < 8; j++)
            #pragma unroll
            for (int q = 0; q < 4; q++) acc[i][j][q] = 0.f;

    const int ar = tid >> 3,  ac = (tid & 7) * 8;    // A: 128r x 64h
    const int br = tid >> 4,  bc = (tid & 15) * 8;   // B: 64r x 128h

    auto load_stage = [&](int s, int k0) {
        __half* As = dynsm + s * STG_SZ;
        __half* Bs = As + STG_A;
        #pragma unroll
        for (int it = 0; it < 4; it++) {
            int r = ar + it * 32;
            cp16(smem_u32(&As[r * LDA_H + ac]), A + (row0 + r) * lda + k0 + ac);
        }
        #pragma unroll
        for (int it = 0; it < 4; it++) {
            int r = br + it * 16;
            cp16(smem_u32(&Bs[r * LDB_H + bc]), B + (long long)(k0 + r) * ldb + col0 + bc);
        }
        cp_commit();
    };

    load_stage(0, 0);
    load_stage(1, GBK);

    const int arow = (lane & 7) + 8 * ((lane >> 3) & 1);
    const int acolb = ((lane >> 4) & 1) * 8;

    const int nsteps = K / GBK;   // 32
    for (int s = 0; s < nsteps; s++) {
        // Load stage (s+2)%3 BEFORE the wait. Safe: that buffer was last read
        // at iteration s-1, whose trailing __syncthreads all warps passed.
        if (s + 2 < nsteps) load_stage((s + 2) % NSTG, (s + 2) * GBK);
        // Need stage s complete; allow up to 2 newer groups in flight.
        if (s + 2 < nsteps)      asm volatile("cp.async.wait_group 2;");
        else if (s + 1 < nsteps) asm volatile("cp.async.wait_group 1;");
        else                     asm volatile("cp.async.wait_group 0;");
        __syncthreads();

        uint32_t aB = smem_u32(dynsm + (s % NSTG) * STG_SZ);
        uint32_t bB = aB + STG_A * 2;
        #pragma unroll
        for (int kk = 0; kk < 4; kk++) {
            uint32_t af[2][4];
            #pragma unroll
            for (int mf = 0; mf < 2; mf++) {
                int r = wm * 32 + mf * 16 + arow;
                int c = kk * 16 + acolb;
                ldsm_x4(af[mf][0], af[mf][1], af[mf][2], af[mf][3], aB + (r * LDA_H + c) * 2);
            }
            #pragma unroll
            for (int nfp = 0; nfp < 4; nfp++) {
                uint32_t b0, b1, b2, b3;
                int r = kk * 16 + arow;
                int c = wn * 64 + nfp * 16 + acolb;
                ldsm_x4_t(b0, b1, b2, b3, bB + (r * LDB_H + c) * 2);
                #pragma unroll
                for (int mf = 0; mf < 2; mf++) {
                    mma_f16(acc[mf][2 * nfp],     af[mf], b0, b1);
                    mma_f16(acc[mf][2 * nfp + 1], af[mf], b2, b3);
                }
            }
        }
        __syncthreads();   // protects (s+3)%3 == s%3 reuse at iteration s+3's load
    }

    const int l4 = lane & 3, l2 = lane >> 2;

    // bias add
    #pragma unroll
    for (int mf = 0; mf < 2; mf++)
        #pragma unroll
        for (int nf = 0; nf < 8; nf++) {
            int colx = col0 + wn * 64 + nf * 8 + 2 * l4;
            float bx = bias[colx], by = bias[colx + 1];
            acc[mf][nf][0] += bx; acc[mf][nf][1] += by;
            acc[mf][nf][2] += bx; acc[mf][nf][3] += by;
        }

    if (MODE == 0) {
        #pragma unroll
        for (int mf = 0; mf < 2; mf++) {
            long long r0 = row0 + wm * 32 + mf * 16 + l2;
            long long r1 = r0 + 8;
            #pragma unroll
            for (int nf = 0; nf < 8; nf++) {
                int colx = col0 + wn * 64 + nf * 8 + 2 * l4;
                float2 v0 = { acc[mf][nf][0], acc[mf][nf][1] };
                float2 v1 = { acc[mf][nf][2], acc[mf][nf][3] };
                *(float2*)(C + r0 * ldc + colx) = v0;
                *(float2*)(C + r1 * ldc + colx) = v1;
            }
        }
        return;
    }

    // ---- MODE 1: fused QKV epilogue ----
    const int seg = col0 >> 11;             // 0:Q 1:K 2:V
    const int hh  = (col0 & 2047) >> 7;
    float* red = (float*)dynsm;             // [128][2]

    if (seg < 2) {
        #pragma unroll
        for (int mf = 0; mf < 2; mf++) {
            float s0 = 0.f, s1 = 0.f;
            #pragma unroll
            for (int nf = 0; nf < 8; nf++) {
                s0 += acc[mf][nf][0] * acc[mf][nf][0] + acc[mf][nf][1] * acc[mf][nf][1];
                s1 += acc[mf][nf][2] * acc[mf][nf][2] + acc[mf][nf][3] * acc[mf][nf][3];
            }
            #pragma unroll
            for (int o = 1; o <= 2; o <<= 1) {
                s0 += __shfl_xor_sync(0xffffffffu, s0, o);
                s1 += __shfl_xor_sync(0xffffffffu, s1, o);
            }
            if (l4 == 0) {
                int rl = wm * 32 + mf * 16 + l2;
                red[rl * 2 + wn] = s0;
                red[(rl + 8) * 2 + wn] = s1;
            }
        }
        __syncthreads();

        const float* scale = (seg == 0) ? q_scale : k_scale;
        const float segq = (seg == 0) ? QK_SCALE : 1.0f;
        __half* Out = (seg == 0) ? Qn : Kn;

        #pragma unroll
        for (int mf = 0; mf < 2; mf++) {
            #pragma unroll
            for (int half = 0; half < 2; half++) {
                int rl = wm * 32 + mf * 16 + half * 8 + l2;
                long long grow = row0 + rl;
                int b = (int)(grow >> 11), l = (int)(grow & 2047);
                float rms = rsqrtf((red[rl * 2] + red[rl * 2 + 1]) * (1.0f / HD) + 1e-6f) * segq;
                long long obase = (((long long)(b * NH + hh)) * SEQ + l) * HD;
                const float* perow = pe + (long long)l * (HD * 2);
                #pragma unroll
                for (int nf = 0; nf < 8; nf++) {
                    int dcol = wn * 64 + nf * 8 + 2 * l4;
                    float e = acc[mf][nf][half * 2]     * rms * scale[dcol];
                    float o = acc[mf][nf][half * 2 + 1] * rms * scale[dcol + 1];
                    float4 rot = *(const float4*)(perow + (dcol >> 1) * 4);
                    *(uint32_t*)(Out + obase + dcol) =
                        pack_h2(rot.x * e + rot.y * o, rot.z * e + rot.w * o);
                }
            }
        }
    } else {
        #pragma unroll
        for (int mf = 0; mf < 2; mf++) {
            #pragma unroll
            for (int half = 0; half < 2; half++) {
                int rl = wm * 32 + mf * 16 + half * 8 + l2;
                long long grow = row0 + rl;
                int b = (int)(grow >> 11), l = (int)(grow & 2047);
                long long obase = (((long long)(b * NH + hh)) * SEQ + l) * HD;
                #pragma unroll
                for (int nf = 0; nf < 8; nf++) {
                    int dcol = wn * 64 + nf * 8 + 2 * l4;
                    *(uint32_t*)(Vh + obase + dcol) =
                        pack_h2(acc[mf][nf][half * 2], acc[mf][nf][half * 2 + 1]);
                }
            }
        }
    }
}

// ---------------------------------------------------------------------------
// Flash attention (exact R12): CTA = 128 Q-rows x head; KV tile 64,
// double-buffered, 2 syncs/tile. Q pre-scaled by QK_SCALE (log2 domain).
// ---------------------------------------------------------------------------
#define LDQ 136
#define KVT 64
#define FTILES (SEQ / KVT)
#define FLASH_SMEM ((128 * LDQ + 4 * KVT * LDQ) * 2)

__global__ __launch_bounds__(256, 2) void flash_attn(
    const __half* __restrict__ Qh, const __half* __restrict__ Kh,
    const __half* __restrict__ Vh, __half* __restrict__ Oh)
{
    extern __shared__ __half sm[];
    __half* Qs = sm;
    __half* Ks = Qs + 128 * LDQ;
    __half* Vs = Ks + 2 * KVT * LDQ;

    const int tid = threadIdx.x, lane = tid & 31, wq = tid >> 5;
    const int bh = blockIdx.y;
    const int b = bh >> 4, h = bh & 15;
    const long long base = (long long)bh * SEQ * HD;
    const __half* Qp = Qh + base + (long long)blockIdx.x * 128 * HD;
    const __half* Kp = Kh + base;
    const __half* Vp = Vh + base;

    const int cr = tid >> 4, cc = (tid & 15) * 8;

    #pragma unroll
    for (int it = 0; it < 8; it++) {
        int r = cr + it * 16;
        cp16(smem_u32(Qs + r * LDQ + cc), Qp + (long long)r * HD + cc);
    }
    cp_commit();

    auto load_kv = [&](int bufi, int t) {
        const __half* kp = Kp + (long long)t * KVT * HD;
        const __half* vp = Vp + (long long)t * KVT * HD;
        __half* kd = Ks + bufi * KVT * LDQ;
        __half* vd = Vs + bufi * KVT * LDQ;
        #pragma unroll
        for (int it = 0; it < 4; it++) {
            int r = cr + it * 16;
            cp16(smem_u32(kd + r * LDQ + cc), kp + (long long)r * HD + cc);
        }
        #pragma unroll
        for (int it = 0; it < 4; it++) {
            int r = cr + it * 16;
            cp16(smem_u32(vd + r * LDQ + cc), vp + (long long)r * HD + cc);
        }
    };

    load_kv(0, 0);
    cp_commit();

    asm volatile("cp.async.wait_group 1;");
    __syncthreads();

    uint32_t qf[8][4];
    {
        int rr = wq * 16 + (lane & 7) + 8 * ((lane >> 3) & 1);
        int c = ((lane >> 4) & 1) * 8;
        uint32_t qB = smem_u32(Qs);
        #pragma unroll
        for (int kk = 0; kk < 8; kk++)
            ldsm_x4(qf[kk][0], qf[kk][1], qf[kk][2], qf[kk][3],
                    qB + (rr * LDQ + kk * 16 + c) * 2);
    }

    float oacc[16][4];
    #pragma unroll
    for (int i = 0; i < 16; i++)
        #pragma unroll
        for (int j = 0; j < 4; j++) oacc[i][j] = 0.f;
    float m0 = -INFINITY, m1 = -INFINITY, l0 = 0.f, l1 = 0.f;

    const int rowS = (lane & 7) + 8 * ((lane >> 4) & 1);
    const int colS = ((lane >> 3) & 1) * 8;
    const int rowV = (lane & 7) + 8 * ((lane >> 3) & 1);
    const int colV = ((lane >> 4) & 1) * 8;
    const uint32_t kB0 = smem_u32(Ks), vB0 = smem_u32(Vs);

    int buf = 0;
    for (int t = 0; t < FTILES; t++) {
        if (t + 1 < FTILES) { load_kv(buf ^ 1, t + 1); cp_commit(); }
        if (t + 1 < FTILES) asm volatile("cp.async.wait_group 1;");
        else                asm volatile("cp.async.wait_group 0;");
        __syncthreads();

        uint32_t kB = kB0 + buf * (KVT * LDQ * 2);
        uint32_t vB = vB0 + buf * (KVT * LDQ * 2);

        float sacc[8][4];
        #pragma unroll
        for (int i = 0; i < 8; i++)
            #pragma unroll
            for (int j = 0; j < 4; j++) sacc[i][j] = 0.f;

        #pragma unroll
        for (int nfp = 0; nfp < 4; nfp++) {
            uint32_t baseN = kB + ((16 * nfp + rowS) * LDQ + colS) * 2;
            #pragma unroll
            for (int kk = 0; kk < 8; kk++) {
                uint32_t b0, b1, b2, b3;
                ldsm_x4(b0, b1, b2, b3, baseN + kk * 32);
                mma_f16(sacc[2 * nfp],     qf[kk], b0, b1);
                mma_f16(sacc[2 * nfp + 1], qf[kk], b2, b3);
            }
        }

        float mt0 = -INFINITY, mt1 = -INFINITY;
        #pragma unroll
        for (int nf = 0; nf < 8; nf++) {
            mt0 = fmaxf(mt0, fmaxf(sacc[nf][0], sacc[nf][1]));
            mt1 = fmaxf(mt1, fmaxf(sacc[nf][2], sacc[nf][3]));
        }
        #pragma unroll
        for (int o = 1; o <= 2; o <<= 1) {
            mt0 = fmaxf(mt0, __shfl_xor_sync(0xffffffffu, mt0, o));
            mt1 = fmaxf(mt1, __shfl_xor_sync(0xffffffffu, mt1, o));
        }
        float mn0 = fmaxf(m0, mt0), mn1 = fmaxf(m1, mt1);
        float cor0 = exp2f(m0 - mn0), cor1 = exp2f(m1 - mn1);
        m0 = mn0; m1 = mn1;

        float rs0 = 0.f, rs1 = 0.f;
        #pragma unroll
        for (int nf = 0; nf < 8; nf++) {
            sacc[nf][0] = exp2f(sacc[nf][0] - mn0);
            sacc[nf][1] = exp2f(sacc[nf][1] - mn0);
            sacc[nf][2] = exp2f(sacc[nf][2] - mn1);
            sacc[nf][3] = exp2f(sacc[nf][3] - mn1);
            rs0 += sacc[nf][0] + sacc[nf][1];
            rs1 += sacc[nf][2] + sacc[nf][3];
        }
        l0 = l0 * cor0 + rs0;
        l1 = l1 * cor1 + rs1;
        #pragma unroll
        for (int nf = 0; nf < 16; nf++) {
            oacc[nf][0] *= cor0; oacc[nf][1] *= cor0;
            oacc[nf][2] *= cor1; oacc[nf][3] *= cor1;
        }

        #pragma unroll
        for (int kk = 0; kk < 4; kk++) {
            uint32_t af[4];
            af[0] = pack_h2(sacc[2 * kk][0],     sacc[2 * kk][1]);
            af[1] = pack_h2(sacc[2 * kk][2],     sacc[2 * kk][3]);
            af[2] = pack_h2(sacc[2 * kk + 1][0], sacc[2 * kk + 1][1]);
            af[3] = pack_h2(sacc[2 * kk + 1][2], sacc[2 * kk + 1][3]);
            uint32_t baseK = vB + ((16 * kk + rowV) * LDQ + colV) * 2;
            #pragma unroll
            for (int nfp = 0; nfp < 8; nfp++) {
                uint32_t b0, b1, b2, b3;
                ldsm_x4_t(b0, b1, b2, b3, baseK + nfp * 32);
                mma_f16(oacc[2 * nfp],     af, b0, b1);
                mma_f16(oacc[2 * nfp + 1], af, b2, b3);
            }
        }
        __syncthreads();
        buf ^= 1;
    }

    #pragma unroll
    for (int o = 1; o <= 2; o <<= 1) {
        l0 += __shfl_xor_sync(0xffffffffu, l0, o);
        l1 += __shfl_xor_sync(0xffffffffu, l1, o);
    }
    float inv0 = 1.0f / l0, inv1 = 1.0f / l1;

    const int l4 = lane & 3, l2 = lane >> 2;
    long long q0 = (long long)blockIdx.x * 128 + wq * 16 + l2;
    #pragma unroll
    for (int nf = 0; nf < 16; nf++) {
        int col = nf * 8 + 2 * l4;
        long long o0 = ((long long)b * SEQ + q0) * DIM + h * HD + col;
        long long o1 = o0 + 8LL * DIM;
        *(uint32_t*)(Oh + o0) = pack_h2(oacc[nf][0] * inv0, oacc[nf][1] * inv0);
        *(uint32_t*)(Oh + o1) = pack_h2(oacc[nf][2] * inv1, oacc[nf][3] * inv1);
    }
}

// ---------------------------------------------------------------------------
extern "C" void kernel_launch(void* const* d_in, const int* in_sizes, int n_in,
                              void* d_out, int out_size)
{
    const float* x       = (const float*)d_in[0];
    const float* pe      = (const float*)d_in[1];
    const float* qkv_w   = (const float*)d_in[2];
    const float* qkv_b   = (const float*)d_in[3];
    const float* q_scale = (const float*)d_in[4];
    const float* k_scale = (const float*)d_in[5];
    const float* proj_w  = (const float*)d_in[6];
    const float* proj_b  = (const float*)d_in[7];
    float* out = (float*)d_out;

    __half *xh, *wqkvh, *wprojh, *Qnh, *Knh, *Vh, *Oh;
    cudaGetSymbolAddress((void**)&xh,     g_xh);
    cudaGetSymbolAddress((void**)&wqkvh,  g_wqkvh);
    cudaGetSymbolAddress((void**)&wprojh, g_wprojh);
    cudaGetSymbolAddress((void**)&Qnh,    g_qnh);
    cudaGetSymbolAddress((void**)&Knh,    g_knh);
    cudaGetSymbolAddress((void**)&Vh,     g_vh);
    cudaGetSymbolAddress((void**)&Oh,     g_oh);

    cudaFuncSetAttribute(gemm_f16<0>, cudaFuncAttributeMaxDynamicSharedMemorySize, GEMM_SMEM);
    cudaFuncSetAttribute(gemm_f16<1>, cudaFuncAttributeMaxDynamicSharedMemorySize, GEMM_SMEM);
    cudaFuncSetAttribute(flash_attn, cudaFuncAttributeMaxDynamicSharedMemorySize, FLASH_SMEM);

    // 0) convert x + both weights to fp16 (one kernel)
    {
        long long total = CN0 + CN1 + CN2;
        convert_all<<<(unsigned)(total / 256), 256>>>(x, qkv_w, proj_w, xh, wqkvh, wprojh);
    }

    // 1) fused QKV gemm -> Qnh (pre-scaled) / Knh / Vh
    gemm_f16<1><<<dim3(QKV_N / 128, ROWS / 128), 256, GEMM_SMEM>>>(
        xh, wqkvh, qkv_b, nullptr, DIM, DIM, QKV_N, 0,
        pe, q_scale, k_scale, Qnh, Knh, Vh);

    // 2) flash attention -> Oh [b,l,h*D+d] fp16
    flash_attn<<<dim3(SEQ / 128, BATCH * NH), 256, FLASH_SMEM>>>(Qnh, Knh, Vh, Oh);

    // 3) out = Oh @ proj_w + proj_b
    gemm_f16<0><<<dim3(DIM / 128, ROWS / 128), 256, GEMM_SMEM>>>(
        Oh, wprojh, proj_b, out, DIM, DIM, DIM, DIM,
        nullptr, nullptr, nullptr, nullptr, nullptr, nullptr);
}

// round 17
// speedup vs baseline: 1.0063x; 1.0063x over previous
#include <cuda_runtime.h>
#include <cuda_fp16.h>
#include <math.h>
#include <stdint.h>

#define BATCH 2
#define SEQ   2048
#define DIM   2048
#define NH    16
#define HD    128
#define QKV_N (3*DIM)
#define ROWS  (BATCH*SEQ)

// 1/sqrt(128) * log2(e) — folded into stored Q
#define QK_SCALE 0.12752798314985582f

// ---------------- scratch (device globals) ----------------
__device__ __half g_xh[(long long)ROWS * DIM];
__device__ __half g_wqkvh[(long long)DIM * QKV_N];
__device__ __half g_wprojh[(long long)DIM * DIM];
__device__ __half g_qnh[(long long)BATCH*NH*SEQ*HD];
__device__ __half g_knh[(long long)BATCH*NH*SEQ*HD];
__device__ __half g_vh [(long long)BATCH*NH*SEQ*HD];
__device__ __half g_oh [(long long)ROWS * DIM];

// ---------------- PTX helpers ----------------
__device__ __forceinline__ uint32_t smem_u32(const void* p) {
    return (uint32_t)__cvta_generic_to_shared(p);
}
__device__ __forceinline__ void ldsm_x4(uint32_t& r0, uint32_t& r1, uint32_t& r2, uint32_t& r3, uint32_t a) {
    asm volatile("ldmatrix.sync.aligned.m8n8.x4.shared.b16 {%0,%1,%2,%3}, [%4];"
                 : "=r"(r0), "=r"(r1), "=r"(r2), "=r"(r3) : "r"(a));
}
__device__ __forceinline__ void ldsm_x4_t(uint32_t& r0, uint32_t& r1, uint32_t& r2, uint32_t& r3, uint32_t a) {
    asm volatile("ldmatrix.sync.aligned.m8n8.x4.trans.shared.b16 {%0,%1,%2,%3}, [%4];"
                 : "=r"(r0), "=r"(r1), "=r"(r2), "=r"(r3) : "r"(a));
}
__device__ __forceinline__ void mma_f16(float* d, const uint32_t* a, uint32_t b0, uint32_t b1) {
    asm volatile("mma.sync.aligned.m16n8k16.row.col.f32.f16.f16.f32 "
                 "{%0,%1,%2,%3}, {%4,%5,%6,%7}, {%8,%9}, {%0,%1,%2,%3};"
                 : "+f"(d[0]), "+f"(d[1]), "+f"(d[2]), "+f"(d[3])
                 : "r"(a[0]), "r"(a[1]), "r"(a[2]), "r"(a[3]), "r"(b0), "r"(b1));
}
__device__ __forceinline__ void cp16(uint32_t dst, const void* src) {
    asm volatile("cp.async.cg.shared.global [%0], [%1], 16;" :: "r"(dst), "l"(src));
}
__device__ __forceinline__ void cp_commit() { asm volatile("cp.async.commit_group;"); }
__device__ __forceinline__ uint32_t pack_h2(float x, float y) {
    __half2 h = __floats2half2_rn(x, y);
    return *(uint32_t*)&h;
}

// ---------------- merged fp32 -> fp16 converter ----------------
#define CN0 ((long long)ROWS * DIM / 8)
#define CN1 ((long long)DIM * QKV_N / 8)
#define CN2 ((long long)DIM * DIM / 8)

__global__ __launch_bounds__(256) void convert_all(
    const float* __restrict__ x,  const float* __restrict__ w1, const float* __restrict__ w2,
    __half* __restrict__ xo, __half* __restrict__ w1o, __half* __restrict__ w2o)
{
    long long i = (long long)blockIdx.x * 256 + threadIdx.x;
    const float* s; __half* d; long long j;
    if (i < CN0)            { s = x;  d = xo;  j = i; }
    else if (i < CN0 + CN1) { s = w1; d = w1o; j = i - CN0; }
    else                    { s = w2; d = w2o; j = i - CN0 - CN1; }
    const float4* s4 = (const float4*)s;
    float4 v0 = s4[2*j], v1 = s4[2*j + 1];
    uint4 o;
    o.x = pack_h2(v0.x, v0.y); o.y = pack_h2(v0.z, v0.w);
    o.z = pack_h2(v1.x, v1.y); o.w = pack_h2(v1.z, v1.w);
    ((uint4*)d)[j] = o;
}

// ---------------------------------------------------------------------------
// fp16 GEMM (NN): C_f32 = A_h[M,K] @ B_h[K,N] + bias   (R12-best config)
// 128x128 CTA tile, 256 threads (8 warps, warp tile 32x64), GBK=64, 2-stage.
// MODE 0: fp32 out + bias
// MODE 1: fused QKV epilogue (tile = one head); Q rms pre-scaled by QK_SCALE.
// ---------------------------------------------------------------------------
#define GBK 64
#define LDA_H 72
#define LDB_H 136
#define STG_A (128 * LDA_H)          // 9216 halves
#define STG_B (GBK * LDB_H)          // 8704 halves
#define STG_SZ (STG_A + STG_B)       // 17920 halves
#define NSTG 2
#define GEMM_SMEM (NSTG * STG_SZ * 2)    // 71680 B

template<int MODE>
__global__ __launch_bounds__(256, 2) void gemm_f16(
    const __half* __restrict__ A, const __half* __restrict__ B,
    const float* __restrict__ bias, float* __restrict__ C,
    int K, int lda, int ldb, int ldc,
    const float* __restrict__ pe,
    const float* __restrict__ q_scale, const float* __restrict__ k_scale,
    __half* __restrict__ Qn, __half* __restrict__ Kn, __half* __restrict__ Vh)
{
    extern __shared__ __half dynsm[];

    const int tid = threadIdx.x, lane = tid & 31, warp = tid >> 5;
    const int wm = warp & 3, wn = warp >> 2;
    const long long row0 = (long long)blockIdx.y * 128;
    const int col0 = blockIdx.x * 128;

    float acc[2][8][4];
    #pragma unroll
    for (int i = 0; i < 2; i++)
        #pragma unroll
        for (int j = 0; j < 8; j++)
            #pragma unroll
            for (int q = 0; q < 4; q++) acc[i][j][q] = 0.f;

    const int ar = tid >> 3,  ac = (tid & 7) * 8;    // A: 128r x 64h
    const int br = tid >> 4,  bc = (tid & 15) * 8;   // B: 64r x 128h

    auto load_stage = [&](int s, int k0) {
        __half* As = dynsm + s * STG_SZ;
        __half* Bs = As + STG_A;
        #pragma unroll
        for (int it = 0; it < 4; it++) {
            int r = ar + it * 32;
            cp16(smem_u32(&As[r * LDA_H + ac]), A + (row0 + r) * lda + k0 + ac);
        }
        #pragma unroll
        for (int it = 0; it < 4; it++) {
            int r = br + it * 16;
            cp16(smem_u32(&Bs[r * LDB_H + bc]), B + (long long)(k0 + r) * ldb + col0 + bc);
        }
    };

    load_stage(0, 0); cp_commit();

    const int arow = (lane & 7) + 8 * ((lane >> 3) & 1);
    const int acolb = ((lane >> 4) & 1) * 8;

    const int nsteps = K / GBK;
    for (int s = 0; s < nsteps; s++) {
        if (s + 1 < nsteps) { load_stage((s + 1) & 1, (s + 1) * GBK); cp_commit(); }
        if (s + 1 < nsteps) asm volatile("cp.async.wait_group 1;");
        else                asm volatile("cp.async.wait_group 0;");
        __syncthreads();

        uint32_t aB = smem_u32(dynsm + (s & 1) * STG_SZ);
        uint32_t bB = smem_u32(dynsm + (s & 1) * STG_SZ + STG_A);
        #pragma unroll
        for (int kk = 0; kk < 4; kk++) {
            uint32_t af[2][4];
            #pragma unroll
            for (int mf = 0; mf < 2; mf++) {
                int r = wm * 32 + mf * 16 + arow;
                int c = kk * 16 + acolb;
                ldsm_x4(af[mf][0], af[mf][1], af[mf][2], af[mf][3], aB + (r * LDA_H + c) * 2);
            }
            #pragma unroll
            for (int nfp = 0; nfp < 4; nfp++) {
                uint32_t b0, b1, b2, b3;
                int r = kk * 16 + arow;
                int c = wn * 64 + nfp * 16 + acolb;
                ldsm_x4_t(b0, b1, b2, b3, bB + (r * LDB_H + c) * 2);
                #pragma unroll
                for (int mf = 0; mf < 2; mf++) {
                    mma_f16(acc[mf][2 * nfp],     af[mf], b0, b1);
                    mma_f16(acc[mf][2 * nfp + 1], af[mf], b2, b3);
                }
            }
        }
        __syncthreads();
    }

    const int l4 = lane & 3, l2 = lane >> 2;

    // bias add
    #pragma unroll
    for (int mf = 0; mf < 2; mf++)
        #pragma unroll
        for (int nf = 0; nf < 8; nf++) {
            int colx = col0 + wn * 64 + nf * 8 + 2 * l4;
            float bx = bias[colx], by = bias[colx + 1];
            acc[mf][nf][0] += bx; acc[mf][nf][1] += by;
            acc[mf][nf][2] += bx; acc[mf][nf][3] += by;
        }

    if (MODE == 0) {
        #pragma unroll
        for (int mf = 0; mf < 2; mf++) {
            long long r0 = row0 + wm * 32 + mf * 16 + l2;
            long long r1 = r0 + 8;
            #pragma unroll
            for (int nf = 0; nf < 8; nf++) {
                int colx = col0 + wn * 64 + nf * 8 + 2 * l4;
                float2 v0 = { acc[mf][nf][0], acc[mf][nf][1] };
                float2 v1 = { acc[mf][nf][2], acc[mf][nf][3] };
                *(float2*)(C + r0 * ldc + colx) = v0;
                *(float2*)(C + r1 * ldc + colx) = v1;
            }
        }
        return;
    }

    // ---- MODE 1: fused QKV epilogue ----
    const int seg = col0 >> 11;             // 0:Q 1:K 2:V
    const int hh  = (col0 & 2047) >> 7;
    float* red = (float*)dynsm;             // [128][2]

    if (seg < 2) {
        #pragma unroll
        for (int mf = 0; mf < 2; mf++) {
            float s0 = 0.f, s1 = 0.f;
            #pragma unroll
            for (int nf = 0; nf < 8; nf++) {
                s0 += acc[mf][nf][0] * acc[mf][nf][0] + acc[mf][nf][1] * acc[mf][nf][1];
                s1 += acc[mf][nf][2] * acc[mf][nf][2] + acc[mf][nf][3] * acc[mf][nf][3];
            }
            #pragma unroll
            for (int o = 1; o <= 2; o <<= 1) {
                s0 += __shfl_xor_sync(0xffffffffu, s0, o);
                s1 += __shfl_xor_sync(0xffffffffu, s1, o);
            }
            if (l4 == 0) {
                int rl = wm * 32 + mf * 16 + l2;
                red[rl * 2 + wn] = s0;
                red[(rl + 8) * 2 + wn] = s1;
            }
        }
        __syncthreads();

        const float* scale = (seg == 0) ? q_scale : k_scale;
        const float segq = (seg == 0) ? QK_SCALE : 1.0f;
        __half* Out = (seg == 0) ? Qn : Kn;

        #pragma unroll
        for (int mf = 0; mf < 2; mf++) {
            #pragma unroll
            for (int half = 0; half < 2; half++) {
                int rl = wm * 32 + mf * 16 + half * 8 + l2;
                long long grow = row0 + rl;
                int b = (int)(grow >> 11), l = (int)(grow & 2047);
                float rms = rsqrtf((red[rl * 2] + red[rl * 2 + 1]) * (1.0f / HD) + 1e-6f) * segq;
                long long obase = (((long long)(b * NH + hh)) * SEQ + l) * HD;
                const float* perow = pe + (long long)l * (HD * 2);
                #pragma unroll
                for (int nf = 0; nf < 8; nf++) {
                    int dcol = wn * 64 + nf * 8 + 2 * l4;
                    float e = acc[mf][nf][half * 2]     * rms * scale[dcol];
                    float o = acc[mf][nf][half * 2 + 1] * rms * scale[dcol + 1];
                    float4 rot = *(const float4*)(perow + (dcol >> 1) * 4);
                    *(uint32_t*)(Out + obase + dcol) =
                        pack_h2(rot.x * e + rot.y * o, rot.z * e + rot.w * o);
                }
            }
        }
    } else {
        #pragma unroll
        for (int mf = 0; mf < 2; mf++) {
            #pragma unroll
            for (int half = 0; half < 2; half++) {
                int rl = wm * 32 + mf * 16 + half * 8 + l2;
                long long grow = row0 + rl;
                int b = (int)(grow >> 11), l = (int)(grow & 2047);
                long long obase = (((long long)(b * NH + hh)) * SEQ + l) * HD;
                #pragma unroll
                for (int nf = 0; nf < 8; nf++) {
                    int dcol = wn * 64 + nf * 8 + 2 * l4;
                    *(uint32_t*)(Vh + obase + dcol) =
                        pack_h2(acc[mf][nf][half * 2], acc[mf][nf][half * 2 + 1]);
                }
            }
        }
    }
}

// ---------------------------------------------------------------------------
// Flash attention (R12): CTA = 128 Q-rows x head; KV tile 64, double-buffered,
// 2 syncs/tile. Q pre-scaled by QK_SCALE (scores in log2 domain).
// ---------------------------------------------------------------------------
#define LDQ 136
#define KVT 64
#define FTILES (SEQ / KVT)
#define FLASH_SMEM ((128 * LDQ + 4 * KVT * LDQ) * 2)

__global__ __launch_bounds__(256, 2) void flash_attn(
    const __half* __restrict__ Qh, const __half* __restrict__ Kh,
    const __half* __restrict__ Vh, __half* __restrict__ Oh)
{
    extern __shared__ __half sm[];
    __half* Qs = sm;
    __half* Ks = Qs + 128 * LDQ;
    __half* Vs = Ks + 2 * KVT * LDQ;

    const int tid = threadIdx.x, lane = tid & 31, wq = tid >> 5;
    const int bh = blockIdx.y;
    const int b = bh >> 4, h = bh & 15;
    const long long base = (long long)bh * SEQ * HD;
    const __half* Qp = Qh + base + (long long)blockIdx.x * 128 * HD;
    const __half* Kp = Kh + base;
    const __half* Vp = Vh + base;

    const int cr = tid >> 4, cc = (tid & 15) * 8;

    #pragma unroll
    for (int it = 0; it < 8; it++) {
        int r = cr + it * 16;
        cp16(smem_u32(Qs + r * LDQ + cc), Qp + (long long)r * HD + cc);
    }
    cp_commit();

    auto load_kv = [&](int bufi, int t) {
        const __half* kp = Kp + (long long)t * KVT * HD;
        const __half* vp = Vp + (long long)t * KVT * HD;
        __half* kd = Ks + bufi * KVT * LDQ;
        __half* vd = Vs + bufi * KVT * LDQ;
        #pragma unroll
        for (int it = 0; it < 4; it++) {
            int r = cr + it * 16;
            cp16(smem_u32(kd + r * LDQ + cc), kp + (long long)r * HD + cc);
        }
        #pragma unroll
        for (int it = 0; it < 4; it++) {
            int r = cr + it * 16;
            cp16(smem_u32(vd + r * LDQ + cc), vp + (long long)r * HD + cc);
        }
    };

    load_kv(0, 0);
    cp_commit();

    asm volatile("cp.async.wait_group 1;");
    __syncthreads();

    uint32_t qf[8][4];
    {
        int rr = wq * 16 + (lane & 7) + 8 * ((lane >> 3) & 1);
        int c = ((lane >> 4) & 1) * 8;
        uint32_t qB = smem_u32(Qs);
        #pragma unroll
        for (int kk = 0; kk < 8; kk++)
            ldsm_x4(qf[kk][0], qf[kk][1], qf[kk][2], qf[kk][3],
                    qB + (rr * LDQ + kk * 16 + c) * 2);
    }

    float oacc[16][4];
    #pragma unroll
    for (int i = 0; i < 16; i++)
        #pragma unroll
        for (int j = 0; j < 4; j++) oacc[i][j] = 0.f;
    float m0 = -INFINITY, m1 = -INFINITY, l0 = 0.f, l1 = 0.f;

    const int rowS = (lane & 7) + 8 * ((lane >> 4) & 1);
    const int colS = ((lane >> 3) & 1) * 8;
    const int rowV = (lane & 7) + 8 * ((lane >> 3) & 1);
    const int colV = ((lane >> 4) & 1) * 8;
    const uint32_t kB0 = smem_u32(Ks), vB0 = smem_u32(Vs);

    int buf = 0;
    for (int t = 0; t < FTILES; t++) {
        if (t + 1 < FTILES) { load_kv(buf ^ 1, t + 1); cp_commit(); }
        if (t + 1 < FTILES) asm volatile("cp.async.wait_group 1;");
        else                asm volatile("cp.async.wait_group 0;");
        __syncthreads();

        uint32_t kB = kB0 + buf * (KVT * LDQ * 2);
        uint32_t vB = vB0 + buf * (KVT * LDQ * 2);

        float sacc[8][4];
        #pragma unroll
        for (int i = 0; i < 8; i++)
            #pragma unroll
            for (int j = 0; j < 4; j++) sacc[i][j] = 0.f;

        #pragma unroll
        for (int nfp = 0; nfp < 4; nfp++) {
            uint32_t baseN = kB + ((16 * nfp + rowS) * LDQ + colS) * 2;
            #pragma unroll
            for (int kk = 0; kk < 8; kk++) {
                uint32_t b0, b1, b2, b3;
                ldsm_x4(b0, b1, b2, b3, baseN + kk * 32);
                mma_f16(sacc[2 * nfp],     qf[kk], b0, b1);
                mma_f16(sacc[2 * nfp + 1], qf[kk], b2, b3);
            }
        }

        float mt0 = -INFINITY, mt1 = -INFINITY;
        #pragma unroll
        for (int nf = 0; nf < 8; nf++) {
            mt0 = fmaxf(mt0, fmaxf(sacc[nf][0], sacc[nf][1]));
            mt1 = fmaxf(mt1, fmaxf(sacc[nf][2], sacc[nf][3]));
        }
        #pragma unroll
        for (int o = 1; o <= 2; o <<= 1) {
            mt0 = fmaxf(mt0, __shfl_xor_sync(0xffffffffu, mt0, o));
            mt1 = fmaxf(mt1, __shfl_xor_sync(0xffffffffu, mt1, o));
        }
        float mn0 = fmaxf(m0, mt0), mn1 = fmaxf(m1, mt1);
        float cor0 = exp2f(m0 - mn0), cor1 = exp2f(m1 - mn1);
        m0 = mn0; m1 = mn1;

        float rs0 = 0.f, rs1 = 0.f;
        #pragma unroll
        for (int nf = 0; nf < 8; nf++) {
            sacc[nf][0] = exp2f(sacc[nf][0] - mn0);
            sacc[nf][1] = exp2f(sacc[nf][1] - mn0);
            sacc[nf][2] = exp2f(sacc[nf][2] - mn1);
            sacc[nf][3] = exp2f(sacc[nf][3] - mn1);
            rs0 += sacc[nf][0] + sacc[nf][1];
            rs1 += sacc[nf][2] + sacc[nf][3];
        }
        l0 = l0 * cor0 + rs0;
        l1 = l1 * cor1 + rs1;
        #pragma unroll
        for (int nf = 0; nf < 16; nf++) {
            oacc[nf][0] *= cor0; oacc[nf][1] *= cor0;
            oacc[nf][2] *= cor1; oacc[nf][3] *= cor1;
        }

        #pragma unroll
        for (int kk = 0; kk < 4; kk++) {
            uint32_t af[4];
            af[0] = pack_h2(sacc[2 * kk][0],     sacc[2 * kk][1]);
            af[1] = pack_h2(sacc[2 * kk][2],     sacc[2 * kk][3]);
            af[2] = pack_h2(sacc[2 * kk + 1][0], sacc[2 * kk + 1][1]);
            af[3] = pack_h2(sacc[2 * kk + 1][2], sacc[2 * kk + 1][3]);
            uint32_t baseK = vB + ((16 * kk + rowV) * LDQ + colV) * 2;
            #pragma unroll
            for (int nfp = 0; nfp < 8; nfp++) {
                uint32_t b0, b1, b2, b3;
                ldsm_x4_t(b0, b1, b2, b3, baseK + nfp * 32);
                mma_f16(oacc[2 * nfp],     af, b0, b1);
                mma_f16(oacc[2 * nfp + 1], af, b2, b3);
            }
        }
        __syncthreads();
        buf ^= 1;
    }

    #pragma unroll
    for (int o = 1; o <= 2; o <<= 1) {
        l0 += __shfl_xor_sync(0xffffffffu, l0, o);
        l1 += __shfl_xor_sync(0xffffffffu, l1, o);
    }
    float inv0 = 1.0f / l0, inv1 = 1.0f / l1;

    const int l4 = lane & 3, l2 = lane >> 2;
    long long q0 = (long long)blockIdx.x * 128 + wq * 16 + l2;
    #pragma unroll
    for (int nf = 0; nf < 16; nf++) {
        int col = nf * 8 + 2 * l4;
        long long o0 = ((long long)b * SEQ + q0) * DIM + h * HD + col;
        long long o1 = o0 + 8LL * DIM;
        *(uint32_t*)(Oh + o0) = pack_h2(oacc[nf][0] * inv0, oacc[nf][1] * inv0);
        *(uint32_t*)(Oh + o1) = pack_h2(oacc[nf][2] * inv1, oacc[nf][3] * inv1);
    }
}

// ---------------------------------------------------------------------------
extern "C" void kernel_launch(void* const* d_in, const int* in_sizes, int n_in,
                              void* d_out, int out_size)
{
    const float* x       = (const float*)d_in[0];
    const float* pe      = (const float*)d_in[1];
    const float* qkv_w   = (const float*)d_in[2];
    const float* qkv_b   = (const float*)d_in[3];
    const float* q_scale = (const float*)d_in[4];
    const float* k_scale = (const float*)d_in[5];
    const float* proj_w  = (const float*)d_in[6];
    const float* proj_b  = (const float*)d_in[7];
    float* out = (float*)d_out;

    __half *xh, *wqkvh, *wprojh, *Qnh, *Knh, *Vh, *Oh;
    cudaGetSymbolAddress((void**)&xh,     g_xh);
    cudaGetSymbolAddress((void**)&wqkvh,  g_wqkvh);
    cudaGetSymbolAddress((void**)&wprojh, g_wprojh);
    cudaGetSymbolAddress((void**)&Qnh,    g_qnh);
    cudaGetSymbolAddress((void**)&Knh,    g_knh);
    cudaGetSymbolAddress((void**)&Vh,     g_vh);
    cudaGetSymbolAddress((void**)&Oh,     g_oh);

    cudaFuncSetAttribute(gemm_f16<0>, cudaFuncAttributeMaxDynamicSharedMemorySize, GEMM_SMEM);
    cudaFuncSetAttribute(gemm_f16<1>, cudaFuncAttributeMaxDynamicSharedMemorySize, GEMM_SMEM);
    cudaFuncSetAttribute(flash_attn, cudaFuncAttributeMaxDynamicSharedMemorySize, FLASH_SMEM);

    // 0) convert x + both weights to fp16 (one kernel)
    {
        long long total = CN0 + CN1 + CN2;
        convert_all<<<(unsigned)(total / 256), 256>>>(x, qkv_w, proj_w, xh, wqkvh, wprojh);
    }

    // 1) fused QKV gemm -> Qnh (pre-scaled) / Knh / Vh
    gemm_f16<1><<<dim3(QKV_N / 128, ROWS / 128), 256, GEMM_SMEM>>>(
        xh, wqkvh, qkv_b, nullptr, DIM, DIM, QKV_N, 0,
        pe, q_scale, k_scale, Qnh, Knh, Vh);

    // 2) flash attention -> Oh [b,l,h*D+d] fp16
    flash_attn<<<dim3(SEQ / 128, BATCH * NH), 256, FLASH_SMEM>>>(Qnh, Knh, Vh, Oh);

    // 3) out = Oh @ proj_w + proj_b
    gemm_f16<0><<<dim3(DIM / 128, ROWS / 128), 256, GEMM_SMEM>>>(
        Oh, wprojh, proj_b, out, DIM, DIM, DIM, DIM,
        nullptr, nullptr, nullptr, nullptr, nullptr, nullptr);
}